// round 17
// baseline (speedup 1.0000x reference)
#include <cuda_runtime.h>
#include <cuda_fp16.h>
#include <cstdint>
#include <math.h>

// ---------------- problem constants ----------------
#define BATCH 8
#define CIN   64
#define COUT  64
#define SDIM  512
#define HH    256
#define WW    256
#define TAPS  9

#define CONV_SCALE (1.0f / 24.0f)
#define MOD_SCALE  (0.04419417382415922f)
#define EPSV       (1e-8f)

// ---------------- device scratch ----------------
// x-transformed demodulated weights fp16: [b][dy*4+t][co][ci]  (12 tiles/b)
__device__ __align__(16) __half g_wt[BATCH * 12 * COUT * CIN];

// ---------------- helpers ----------------
__device__ __forceinline__ uint32_t smem_u32(const void* p) {
    uint32_t a;
    asm("{ .reg .u64 t; cvta.to.shared.u64 t, %1; cvt.u32.u64 %0, t; }" : "=r"(a) : "l"(p));
    return a;
}
__device__ __forceinline__ void ldsm4(uint32_t (&r)[4], uint32_t addr) {
    asm volatile("ldmatrix.sync.aligned.m8n8.x4.shared.b16 {%0,%1,%2,%3}, [%4];"
                 : "=r"(r[0]), "=r"(r[1]), "=r"(r[2]), "=r"(r[3]) : "r"(addr));
}
__device__ __forceinline__ void mma16816(float (&c)[4], const uint32_t (&a)[4],
                                         const uint32_t b0, const uint32_t b1) {
    asm volatile(
        "mma.sync.aligned.m16n8k16.row.col.f32.f16.f16.f32 "
        "{%0,%1,%2,%3}, {%4,%5,%6,%7}, {%8,%9}, {%0,%1,%2,%3};"
        : "+f"(c[0]), "+f"(c[1]), "+f"(c[2]), "+f"(c[3])
        : "r"(a[0]), "r"(a[1]), "r"(a[2]), "r"(a[3]), "r"(b0), "r"(b1));
}
__device__ __forceinline__ uint32_t hadd2u(uint32_t a, uint32_t b) {
    uint32_t d;
    asm("add.f16x2 %0, %1, %2;" : "=r"(d) : "r"(a), "r"(b));
    return d;
}
__device__ __forceinline__ uint32_t hsub2u(uint32_t a, uint32_t b) {
    uint32_t d;
    asm("sub.f16x2 %0, %1, %2;" : "=r"(d) : "r"(a), "r"(b));
    return d;
}
__device__ __forceinline__ void cpasync16(uint32_t dst, const void* src) {
    asm volatile("cp.async.cg.shared.global [%0], [%1], 16;" :: "r"(dst), "l"(src) : "memory");
}
__device__ __forceinline__ void cpcommit() { asm volatile("cp.async.commit_group;" ::: "memory"); }
__device__ __forceinline__ void cpwait0()  { asm volatile("cp.async.wait_group 0;" ::: "memory"); }

__device__ __forceinline__ uint32_t sw128(uint32_t o) { return o ^ ((o >> 3) & 0x70u); }

// ---------------- kernel A: style + demod + x-Winograd W transform ---------
__global__ __launch_bounds__(512, 2)
void demod_kernel(const float* __restrict__ style,
                  const float* __restrict__ mw,
                  const float* __restrict__ mb,
                  const float* __restrict__ w) {
    const int cog = blockIdx.x;
    const int b   = blockIdx.y;
    const int tid  = threadIdx.x;
    const int wid  = tid >> 5;
    const int lane = tid & 31;

    __shared__ float sdot[64];

    {
        int ci = tid >> 3;
        int j  = tid & 7;
        const float* sp = style + (size_t)b * SDIM;
        const float* wp = mw + (size_t)ci * SDIM;
        float sum = 0.f;
        #pragma unroll 8
        for (int t = 0; t < 64; t++)
            sum += sp[j + 8 * t] * wp[j + 8 * t];
        sum += __shfl_xor_sync(0xFFFFFFFFu, sum, 4);
        sum += __shfl_xor_sync(0xFFFFFFFFu, sum, 2);
        sum += __shfl_xor_sync(0xFFFFFFFFu, sum, 1);
        if (j == 0) sdot[ci] = sum * MOD_SCALE + mb[ci];
    }
    __syncthreads();

    const int co = cog * 16 + wid;
    const float* wrow = w + (size_t)co * 576;
    float v[2][9];
    float sumsq = 0.f;
    #pragma unroll
    for (int cih = 0; cih < 2; cih++) {
        int ci = lane + 32 * cih;
        float sd = sdot[ci];
        #pragma unroll
        for (int tap = 0; tap < 9; tap++) {
            float x = CONV_SCALE * wrow[ci * 9 + tap] * sd;
            v[cih][tap] = x;
            sumsq += x * x;
        }
    }
    #pragma unroll
    for (int off = 16; off > 0; off >>= 1)
        sumsq += __shfl_xor_sync(0xFFFFFFFFu, sumsq, off);
    float dm = rsqrtf(sumsq + EPSV);

    #pragma unroll
    for (int cih = 0; cih < 2; cih++) {
        int ci = lane + 32 * cih;
        #pragma unroll
        for (int dy = 0; dy < 3; dy++) {
            float w0 = v[cih][dy * 3 + 0] * dm;
            float w1 = v[cih][dy * 3 + 1] * dm;
            float w2 = v[cih][dy * 3 + 2] * dm;
            float t0 = w0;
            float t1 = (w0 + w1 + w2) * 0.5f;
            float t2 = (w0 - w1 + w2) * 0.5f;
            float t3 = w2;
            size_t base = (((size_t)b * 12 + dy * 4) * COUT + co) * CIN + ci;
            g_wt[base]                          = __float2half_rn(t0);
            g_wt[base + (size_t)COUT * CIN]     = __float2half_rn(t1);
            g_wt[base + (size_t)2 * COUT * CIN] = __float2half_rn(t2);
            g_wt[base + (size_t)3 * COUT * CIN] = __float2half_rn(t3);
        }
    }
}

// ---------------- kernel B: persistent Winograd-x conv, single-row ---------
// Work unit = chunk (xh, y4chunk, b): 128 out px (= 64 tiles) x 64co x 4 rows.
// 8 warps (256 thr): 4 in M (16 tiles) x 2 in N (32co). Rows processed singly;
// A fragments transformed on demand per (kc,dy) -> small live register set.
#define W_OFF       0u
#define W_BYTES     98304u                        // 12 x 64 x 128B
#define RING_OFF    98304u
#define SLOT_STRIDE 16640u                        // 2 planes x 65 x 128B
#define PLANE_E     8320u
#define STAGE_OFF   (RING_OFF + 5u * SLOT_STRIDE) // 181504
#define STAGE_W     136
#define SMEM_TOTAL  (STAGE_OFF + 64u * STAGE_W * 4u)   // 216320

#define NCTA        148

__global__ __launch_bounds__(256, 1)
void conv_kernel(const float* __restrict__ in, float* __restrict__ out) {
    extern __shared__ char smem[];
    const uint32_t sb = smem_u32(smem);
    const int tid  = threadIdx.x;
    const int wid  = tid >> 5;
    const int lane = tid & 31;

    const int mwarp = wid & 3;            // 4 x 16 tiles
    const int nwarp = wid >> 2;           // 2 x 32 co
    const uint32_t mt  = mwarp * 16;
    const uint32_t co0 = nwarp * 32;

    const uint32_t arow = lane & 15;
    const uint32_t khA  = ((lane >> 4) & 1) * 16;
    const uint32_t brow = (lane & 7) | ((lane >> 1) & 8);
    const uint32_t khB  = ((lane >> 3) & 1) * 16;

    // chunk range: 136 CTAs x 7, 12 CTAs x 6  (1024 = 136*7 + 12*6)
    const int cta = blockIdx.x;
    int c, cnt;
    if (cta < 136) { c = cta * 7;               cnt = 7; }
    else           { c = 952 + (cta - 136) * 6; cnt = 6; }

    float* sOut = (float*)(smem + STAGE_OFF);    // [64co][132px] f32 (reuses stage)
    const int eg = lane >> 2;                    // fragment row 0..7
    const int tq = lane & 3;                     // fragment col pair

    int last_b = -1;

    while (cnt > 0) {
        const int col    = c >> 6;          // 16 columns = b(8) x xh(2)
        const int within = c & 63;
        const int b  = col >> 1;
        const int x0 = (col & 1) * 128;
        const int run = min(cnt, 64 - within);
        const int y0r = within * 4;
        const int nrows = run * 4;

        // ---- stage one raw fp32 input row (words: gx = x0-4+w) ----
        auto stage_async = [&](int iy) {
            if ((unsigned)iy >= 256u) return;
            #pragma unroll
            for (int it = 0; it < 9; it++) {
                int idx = tid + 256 * it;        // 64 ci x 34 chunks = 2176
                if (idx < 2176) {
                    int ci = idx / 34;
                    int cc = idx - ci * 34;
                    int gx0 = x0 - 4 + 4 * cc;
                    uint32_t doff = STAGE_OFF + (uint32_t)(ci * STAGE_W + 4 * cc) * 4u;
                    if ((unsigned)gx0 <= 252u) {
                        cpasync16(sb + doff,
                                  in + (((size_t)(b * CIN + ci)) * HH + iy) * WW + gx0);
                    } else {
                        *(uint4*)(smem + doff) = make_uint4(0, 0, 0, 0);
                    }
                }
            }
        };

        // ---- convert staged fp32 row -> polyphase fp16 ring slot ----
        // O[m] = in[x0-1+2m] (word 2m+3), E[m] = in[x0+2m] (word 2m+4), m=0..64
        auto convert_row = [&](int iy) {
            const uint32_t roff = RING_OFF
                + ((uint32_t)((iy + 1) % 5)) * SLOT_STRIDE;
            const bool valid = ((unsigned)iy < 256u);
            const float* st = (const float*)(smem + STAGE_OFF);
            const int g = wid;                   // ci group 8g..8g+7
            #pragma unroll
            for (int h = 0; h < 2; h++) {        // 0 = O plane, 1 = E plane
                #pragma unroll
                for (int it = 0; it < 3; it++) {
                    int m = it * 32 + lane;
                    if (it == 2 && lane >= 1) break;   // m <= 64
                    int word = 2 * m + 3 + h;
                    float vv[8];
                    #pragma unroll
                    for (int k = 0; k < 8; k++)
                        vv[k] = valid ? st[(g * 8 + k) * STAGE_W + word] : 0.f;
                    uint32_t u[4];
                    #pragma unroll
                    for (int k = 0; k < 4; k++) {
                        __half2 hp = __floats2half2_rn(vv[2 * k], vv[2 * k + 1]);
                        u[k] = *reinterpret_cast<uint32_t*>(&hp);
                    }
                    *(uint4*)(smem + roff + (uint32_t)h * PLANE_E
                              + sw128((uint32_t)m * 128u + (uint32_t)g * 16u))
                        = make_uint4(u[0], u[1], u[2], u[3]);
                }
            }
        };

        // ---- run prologue: W (if b changed) + prime input rows y0r-1..y0r+1 --
        if (b != last_b) {
            const uint4* ws = ((const uint4*)g_wt) + (size_t)b * 6144;
            for (int j = tid; j < 6144; j += 256) {
                uint32_t o = (uint32_t)j << 4;
                cpasync16(sb + W_OFF + sw128(o), ws + j);
            }
            cpcommit();
            last_b = b;
        }
        #pragma unroll 1
        for (int rnd = 0; rnd < 3; rnd++) {
            stage_async(y0r - 1 + rnd);
            cpcommit();
            cpwait0();
            __syncthreads();
            convert_row(y0r - 1 + rnd);
            __syncthreads();
        }

        // ---- continuous row loop across the whole run ----
        for (int q = 0; q < nrows; q++) {
            const int y = y0r + q;
            const bool more = (q < nrows - 1);

            if (more) { stage_async(y + 2); cpcommit(); }

            float acc[4][4][4];               // [t][nf][c]
            #pragma unroll
            for (int t = 0; t < 4; t++)
                #pragma unroll
                for (int nf = 0; nf < 4; nf++)
                    #pragma unroll
                    for (int cc = 0; cc < 4; cc++) acc[t][nf][cc] = 0.f;

            #pragma unroll
            for (int kc = 0; kc < 4; kc++) {
                const uint32_t kb = (uint32_t)kc * 32u;
                #pragma unroll
                for (int dy = 0; dy < 3; dy++) {
                    // input row iy = y-1+dy -> slot (y+dy)%5
                    const uint32_t slot = sb + RING_OFF
                        + ((uint32_t)((y + dy) % 5)) * SLOT_STRIDE;
                    uint32_t O[4], E[4], Op[4], Ep[4];
                    const uint32_t ao = sw128((mt + arow) * 128u + kb + khA);
                    const uint32_t a1 = sw128((mt + 1 + arow) * 128u + kb + khA);
                    ldsm4(O,  slot + ao);
                    ldsm4(E,  slot + PLANE_E + ao);
                    ldsm4(Op, slot + a1);
                    ldsm4(Ep, slot + PLANE_E + a1);
                    uint32_t at[4][4];
                    #pragma unroll
                    for (int i = 0; i < 4; i++) {
                        at[0][i] = hsub2u(O[i], Op[i]);   // d0 - d2
                        at[1][i] = hadd2u(E[i], Op[i]);   // d1 + d2
                        at[2][i] = hsub2u(Op[i], E[i]);   // d2 - d1
                        at[3][i] = hsub2u(E[i], Ep[i]);   // d1 - d3
                    }
                    #pragma unroll
                    for (int t = 0; t < 4; t++) {
                        const uint32_t tt = (uint32_t)(dy * 4 + t);
                        uint32_t wa[4], wb[4];
                        ldsm4(wa, sb + W_OFF
                              + sw128((tt * 64u + co0 + brow) * 128u + kb + khB));
                        ldsm4(wb, sb + W_OFF
                              + sw128((tt * 64u + co0 + 16u + brow) * 128u + kb + khB));
                        mma16816(acc[t][0], at[t], wa[0], wa[1]);
                        mma16816(acc[t][1], at[t], wa[2], wa[3]);
                        mma16816(acc[t][2], at[t], wb[0], wb[1]);
                        mma16816(acc[t][3], at[t], wb[2], wb[3]);
                    }
                }
            }

            if (more) {
                cpwait0();
                __syncthreads();
                convert_row(y + 2);              // -> slot (y+3)%5 (free)
            }
            __syncthreads();

            // ---- epilogue: inverse transform + smem transpose + stores ----
            #pragma unroll
            for (int nf = 0; nf < 4; nf++) {
                #pragma unroll
                for (int cc = 0; cc < 4; cc++) {
                    int p  = cc & 1;
                    int g2 = cc >> 1;
                    int tile = mt + eg + g2 * 8;
                    int co   = co0 + nf * 8 + 2 * tq + p;
                    float oe = acc[0][nf][cc] + acc[1][nf][cc] + acc[2][nf][cc];
                    float oo = acc[1][nf][cc] - acc[2][nf][cc] - acc[3][nf][cc];
                    sOut[co * 132 + 2 * tile]     = oe;
                    sOut[co * 132 + 2 * tile + 1] = oo;
                }
            }
            __syncthreads();
            #pragma unroll
            for (int k = 0; k < 8; k++) {
                int idx = tid + 256 * k;        // 2048 float4
                int co = idx >> 5;
                int qq = idx & 31;
                float4 vv = *(float4*)&sOut[co * 132 + qq * 4];
                *(float4*)(out + (((size_t)b * COUT + co) * HH + y) * WW
                           + x0 + qq * 4) = vv;
            }
            __syncthreads();
        }

        c   += run;
        cnt -= run;
    }
}

// ---------------- launch ----------------
extern "C" void kernel_launch(void* const* d_in, const int* in_sizes, int n_in,
                              void* d_out, int out_size) {
    const float* input      = (const float*)d_in[0];
    const float* style      = (const float*)d_in[1];
    const float* weight     = (const float*)d_in[2];
    const float* mod_weight = (const float*)d_in[3];
    const float* mod_bias   = (const float*)d_in[4];
    float* out = (float*)d_out;

    cudaFuncSetAttribute(conv_kernel,
                         cudaFuncAttributeMaxDynamicSharedMemorySize, SMEM_TOTAL);

    demod_kernel<<<dim3(4, BATCH), 512>>>(style, mod_weight, mod_bias, weight);
    conv_kernel<<<NCTA, 256, SMEM_TOTAL>>>(input, out);
}